// round 5
// baseline (speedup 1.0000x reference)
#include <cuda_runtime.h>
#include <math.h>

#define B  8
#define NV 8192
#define E  32768
#define BC 24   // B*3

#define GB_THREADS   128
#define N_PER_THREAD 4
#define N_PER_BLOCK  (GB_THREADS * N_PER_THREAD)   // 512
#define N_TILES      (NV / N_PER_BLOCK)            // 16
#define E_SPLITS     32
#define E_PER_SPLIT  (E / E_SPLITS)                // 1024
#define E_CHUNK      64

// Scratch (static device globals — no runtime allocation)
__device__ float g_M[E * BC];                      // 3 MB:  M[e][b*3+c]
__device__ float g_part[E_SPLITS * BC * NV];       // 24 MB: partial L_vert per e-split

// ---------- packed f32x2 helpers (Blackwell-only; ptxas won't auto-fuse) ----------
__device__ __forceinline__ unsigned long long pack2(float x, float y) {
    unsigned long long r;
    asm("mov.b64 %0, {%1, %2};" : "=l"(r) : "f"(x), "f"(y));
    return r;
}
__device__ __forceinline__ void unpack2(unsigned long long v, float& x, float& y) {
    asm("mov.b64 {%0, %1}, %2;" : "=f"(x), "=f"(y) : "l"(v));
}
__device__ __forceinline__ unsigned long long fma2(unsigned long long a,
                                                   unsigned long long b,
                                                   unsigned long long c) {
    unsigned long long d;
    asm("fma.rn.f32x2 %0, %1, %2, %3;" : "=l"(d) : "l"(a), "l"(b), "l"(c));
    return d;
}

// ---------------------------------------------------------------------------
// Kernel 1: per-(b,e) constraint solve. Writes L_new directly to d_out and
// M[e][b*3+c] to scratch (contiguous 24 floats per e for the GEMM stage).
// ---------------------------------------------------------------------------
__global__ void prep_kernel(const float* __restrict__ Vp,   // (B,NV,3)
                            const float* __restrict__ L,    // (B,E,1)
                            const float* __restrict__ Vw,   // (B,NV,1)
                            const float* __restrict__ Vc,   // (B,1,1)
                            const int*   __restrict__ Cd,   // (E,2)
                            const float* __restrict__ Cid,  // (E,1)
                            float*       __restrict__ out)
{
    int idx = blockIdx.x * blockDim.x + threadIdx.x;
    if (idx >= B * E) return;
    int e = idx & (E - 1);       // E = 2^15
    int b = idx >> 15;

    int i = Cd[2 * e];
    int j = Cd[2 * e + 1];

    const float* vi = Vp + ((size_t)b * NV + i) * 3;
    const float* vj = Vp + ((size_t)b * NV + j) * 3;
    float nx = vi[0] - vj[0];
    float ny = vi[1] - vj[1];
    float nz = vi[2] - vj[2];
    float D  = sqrtf(nx * nx + ny * ny + nz * nz);
    float C  = D - Cid[e];
    float inv = 1.0f / (D + 1e-8f);

    float A  = Vc[b];
    float S  = Vw[b * NV + i] + Vw[b * NV + j];
    float lv = L[b * E + e];
    float Ld = (S == 0.0f) ? 0.0f : (-C - A * lv) / (S + A);

    // L_new goes directly into output (after the V_predict_new block)
    out[(size_t)B * NV * 3 + (size_t)b * E + e] = lv + Ld;

    float s = Ld * inv;
    g_M[(size_t)e * BC + b * 3 + 0] = s * nx;
    g_M[(size_t)e * BC + b * 3 + 1] = s * ny;
    g_M[(size_t)e * BC + b * 3 + 2] = s * nz;
}

// ---------------------------------------------------------------------------
// Kernel 2: skinny GEMM  L_vert[bc][n] = sum_e M[e][bc] * C_mtx[e][n]
// Split-K over e (deterministic partials), thread owns 4 consecutive n.
// Inner loop uses packed fma.rn.f32x2: 48 packed FMAs per e per thread.
// ---------------------------------------------------------------------------
__global__ void __launch_bounds__(GB_THREADS, 3)
gemm_kernel(const float* __restrict__ Cm)
{
    __shared__ __align__(16) float sM[E_CHUNK * BC];

    int tile  = blockIdx.x % N_TILES;
    int split = blockIdx.x / N_TILES;
    int n0 = tile * N_PER_BLOCK + threadIdx.x * N_PER_THREAD;
    int e_begin = split * E_PER_SPLIT;

    unsigned long long acc[12][4];
#pragma unroll
    for (int q = 0; q < 12; q++)
#pragma unroll
        for (int n = 0; n < 4; n++) acc[q][n] = 0ull;

    for (int ec = 0; ec < E_PER_SPLIT; ec += E_CHUNK) {
        __syncthreads();
        const float* src = g_M + (size_t)(e_begin + ec) * BC;
        for (int k = threadIdx.x; k < E_CHUNK * BC; k += GB_THREADS)
            sM[k] = src[k];
        __syncthreads();

        for (int ee = 0; ee < E_CHUNK; ee++) {
            size_t e = (size_t)(e_begin + ec + ee);
            float4 cv = __ldcs((const float4*)(Cm + e * NV + n0));  // streaming, read-once
            unsigned long long c0 = pack2(cv.x, cv.x);
            unsigned long long c1 = pack2(cv.y, cv.y);
            unsigned long long c2 = pack2(cv.z, cv.z);
            unsigned long long c3 = pack2(cv.w, cv.w);
            const unsigned long long* mp =
                (const unsigned long long*)(sM + ee * BC);  // 12 bc-pairs
#pragma unroll
            for (int q = 0; q < 12; q++) {
                unsigned long long m = mp[q];   // {M[e][2q], M[e][2q+1]} broadcast LDS.64
                acc[q][0] = fma2(m, c0, acc[q][0]);
                acc[q][1] = fma2(m, c1, acc[q][1]);
                acc[q][2] = fma2(m, c2, acc[q][2]);
                acc[q][3] = fma2(m, c3, acc[q][3]);
            }
        }
    }

    // Write partials: one coalesced float4 per bc row
#pragma unroll
    for (int q = 0; q < 12; q++) {
        float lo[4], hi[4];
#pragma unroll
        for (int n = 0; n < 4; n++) unpack2(acc[q][n], lo[n], hi[n]);
        float* row0 = g_part + ((size_t)(split * BC + 2 * q)     ) * NV + n0;
        float* row1 = g_part + ((size_t)(split * BC + 2 * q + 1) ) * NV + n0;
        *(float4*)row0 = make_float4(lo[0], lo[1], lo[2], lo[3]);
        *(float4*)row1 = make_float4(hi[0], hi[1], hi[2], hi[3]);
    }
}

// ---------------------------------------------------------------------------
// Kernel 3: reduce split-K partials + epilogue V_predict + V_w * L_vert
// ---------------------------------------------------------------------------
__global__ void final_kernel(const float* __restrict__ Vp,
                             const float* __restrict__ Vw,
                             float*       __restrict__ out)
{
    int idx = blockIdx.x * blockDim.x + threadIdx.x;   // over B*NV
    if (idx >= B * NV) return;
    int n = idx & (NV - 1);    // NV = 2^13
    int b = idx >> 13;
    float w = Vw[idx];
#pragma unroll
    for (int c = 0; c < 3; c++) {
        float s = 0.0f;
#pragma unroll
        for (int sp = 0; sp < E_SPLITS; sp++)
            s += g_part[((size_t)(sp * BC + b * 3 + c)) * NV + n];
        out[(size_t)idx * 3 + c] = Vp[(size_t)idx * 3 + c] + w * s;
    }
}

extern "C" void kernel_launch(void* const* d_in, const int* in_sizes, int n_in,
                              void* d_out, int out_size)
{
    const float* Vp  = (const float*)d_in[0];
    const float* L   = (const float*)d_in[1];
    const float* Vw  = (const float*)d_in[2];
    const float* Vc  = (const float*)d_in[3];
    const int*   Cd  = (const int*)  d_in[4];
    const float* Cid = (const float*)d_in[5];
    const float* Cm  = (const float*)d_in[6];
    float* out = (float*)d_out;

    prep_kernel <<<(B * E + 255) / 256, 256>>>(Vp, L, Vw, Vc, Cd, Cid, out);
    gemm_kernel <<<N_TILES * E_SPLITS, GB_THREADS>>>(Cm);
    final_kernel<<<(B * NV + 255) / 256, 256>>>(Vp, Vw, out);
}

// round 16
// speedup vs baseline: 1.0620x; 1.0620x over previous
#include <cuda_runtime.h>
#include <math.h>

#define B  8
#define NV 8192
#define E  32768
#define BC 24   // B*3

#define GB_THREADS   128
#define N_PER_THREAD 4
#define N_PER_BLOCK  (GB_THREADS * N_PER_THREAD)   // 512
#define N_TILES      (NV / N_PER_BLOCK)            // 16
#define E_SPLITS     37                            // 16*37 = 592 = 148 SMs * 4 blocks
#define E_CHUNK      128

// Scratch (static device globals — no runtime allocation)
__device__ float g_M[E * BC];                         // 3 MB:  M[e][b*3+c]
__device__ float g_part[E_SPLITS * BC * NV];          // 29 MB: partial L_vert per e-split

// ---------- packed f32x2 helpers (Blackwell-only; ptxas won't auto-fuse) ----------
__device__ __forceinline__ unsigned long long pack2(float x, float y) {
    unsigned long long r;
    asm("mov.b64 %0, {%1, %2};" : "=l"(r) : "f"(x), "f"(y));
    return r;
}
__device__ __forceinline__ void unpack2(unsigned long long v, float& x, float& y) {
    asm("mov.b64 {%0, %1}, %2;" : "=f"(x), "=f"(y) : "l"(v));
}
__device__ __forceinline__ unsigned long long fma2(unsigned long long a,
                                                   unsigned long long b,
                                                   unsigned long long c) {
    unsigned long long d;
    asm("fma.rn.f32x2 %0, %1, %2, %3;" : "=l"(d) : "l"(a), "l"(b), "l"(c));
    return d;
}

// ---------------------------------------------------------------------------
// Kernel 1: per-(b,e) constraint solve. Writes L_new directly to d_out and
// M[e][b*3+c] to scratch (contiguous 24 floats per e for the GEMM stage).
// ---------------------------------------------------------------------------
__global__ void prep_kernel(const float* __restrict__ Vp,   // (B,NV,3)
                            const float* __restrict__ L,    // (B,E,1)
                            const float* __restrict__ Vw,   // (B,NV,1)
                            const float* __restrict__ Vc,   // (B,1,1)
                            const int*   __restrict__ Cd,   // (E,2)
                            const float* __restrict__ Cid,  // (E,1)
                            float*       __restrict__ out)
{
    int idx = blockIdx.x * blockDim.x + threadIdx.x;
    if (idx >= B * E) return;
    int e = idx & (E - 1);       // E = 2^15
    int b = idx >> 15;

    int i = Cd[2 * e];
    int j = Cd[2 * e + 1];

    const float* vi = Vp + ((size_t)b * NV + i) * 3;
    const float* vj = Vp + ((size_t)b * NV + j) * 3;
    float nx = vi[0] - vj[0];
    float ny = vi[1] - vj[1];
    float nz = vi[2] - vj[2];
    float D  = sqrtf(nx * nx + ny * ny + nz * nz);
    float C  = D - Cid[e];
    float inv = 1.0f / (D + 1e-8f);

    float A  = Vc[b];
    float S  = Vw[b * NV + i] + Vw[b * NV + j];
    float lv = L[b * E + e];
    float Ld = (S == 0.0f) ? 0.0f : (-C - A * lv) / (S + A);

    // L_new goes directly into output (after the V_predict_new block)
    out[(size_t)B * NV * 3 + (size_t)b * E + e] = lv + Ld;

    float s = Ld * inv;
    g_M[(size_t)e * BC + b * 3 + 0] = s * nx;
    g_M[(size_t)e * BC + b * 3 + 1] = s * ny;
    g_M[(size_t)e * BC + b * 3 + 2] = s * nz;
}

// ---------------------------------------------------------------------------
// Kernel 2: skinny GEMM  L_vert[bc][n] = sum_e M[e][bc] * C_mtx[e][n]
// grid = 16 n-tiles x 37 e-splits = 592 = 148 SMs * 4 blocks (one clean wave).
// Register prefetch (distance 1) on the streaming C_mtx load hides DRAM latency.
// ---------------------------------------------------------------------------
__global__ void __launch_bounds__(GB_THREADS, 4)
gemm_kernel(const float* __restrict__ Cm)
{
    __shared__ __align__(16) float sM[E_CHUNK * BC];   // 12 KB

    int tile  = blockIdx.x & (N_TILES - 1);
    int split = blockIdx.x >> 4;
    int n0 = tile * N_PER_BLOCK + threadIdx.x * N_PER_THREAD;
    int e0 = (int)(((long long)split       * E) / E_SPLITS);
    int e1 = (int)(((long long)(split + 1) * E) / E_SPLITS);

    unsigned long long acc[48];
#pragma unroll
    for (int k = 0; k < 48; k++) acc[k] = 0ull;

    // prefetch first C row
    float4 cv = __ldcs((const float4*)(Cm + (size_t)e0 * NV + n0));

    int e = e0;
    for (int ec = e0; ec < e1; ec += E_CHUNK) {
        int ce = min(ec + E_CHUNK, e1);
        __syncthreads();
        {   // stage M chunk: (ce-ec)*24 floats = (ce-ec)*6 float4 (e*96B is 16B-aligned)
            const float4* src = (const float4*)(g_M + (size_t)ec * BC);
            float4* dst = (float4*)sM;
            int nf4 = (ce - ec) * 6;
            for (int k = threadIdx.x; k < nf4; k += GB_THREADS) dst[k] = src[k];
        }
        __syncthreads();

        for (; e < ce; e++) {
            // prefetch next C row (clamped; redundant reload of e0 on last iter — L2 hit)
            int en = (e + 1 < e1) ? e + 1 : e0;
            float4 nv = __ldcs((const float4*)(Cm + (size_t)en * NV + n0));

            unsigned long long c0 = pack2(cv.x, cv.x);
            unsigned long long c1 = pack2(cv.y, cv.y);
            unsigned long long c2 = pack2(cv.z, cv.z);
            unsigned long long c3 = pack2(cv.w, cv.w);
            const unsigned long long* mp =
                (const unsigned long long*)(sM + (e - ec) * BC);  // 12 bc-pairs
#pragma unroll
            for (int q = 0; q < 12; q++) {
                unsigned long long m = mp[q];   // {M[e][2q], M[e][2q+1]} broadcast LDS.64
                acc[q * 4 + 0] = fma2(m, c0, acc[q * 4 + 0]);
                acc[q * 4 + 1] = fma2(m, c1, acc[q * 4 + 1]);
                acc[q * 4 + 2] = fma2(m, c2, acc[q * 4 + 2]);
                acc[q * 4 + 3] = fma2(m, c3, acc[q * 4 + 3]);
            }
            cv = nv;
        }
    }

    // Write partials: one coalesced float4 per bc row
#pragma unroll
    for (int q = 0; q < 12; q++) {
        float lo[4], hi[4];
#pragma unroll
        for (int n = 0; n < 4; n++) unpack2(acc[q * 4 + n], lo[n], hi[n]);
        float* row0 = g_part + ((size_t)(split * BC + 2 * q)    ) * NV + n0;
        float* row1 = g_part + ((size_t)(split * BC + 2 * q + 1)) * NV + n0;
        *(float4*)row0 = make_float4(lo[0], lo[1], lo[2], lo[3]);
        *(float4*)row1 = make_float4(hi[0], hi[1], hi[2], hi[3]);
    }
}

// ---------------------------------------------------------------------------
// Kernel 3: reduce split-K partials + epilogue V_predict + V_w * L_vert
// ---------------------------------------------------------------------------
__global__ void final_kernel(const float* __restrict__ Vp,
                             const float* __restrict__ Vw,
                             float*       __restrict__ out)
{
    int idx = blockIdx.x * blockDim.x + threadIdx.x;   // over B*NV
    if (idx >= B * NV) return;
    int n = idx & (NV - 1);    // NV = 2^13
    int b = idx >> 13;
    float w = Vw[idx];
#pragma unroll
    for (int c = 0; c < 3; c++) {
        float s = 0.0f;
#pragma unroll
        for (int sp = 0; sp < E_SPLITS; sp++)
            s += g_part[((size_t)(sp * BC + b * 3 + c)) * NV + n];
        out[(size_t)idx * 3 + c] = Vp[(size_t)idx * 3 + c] + w * s;
    }
}

extern "C" void kernel_launch(void* const* d_in, const int* in_sizes, int n_in,
                              void* d_out, int out_size)
{
    const float* Vp  = (const float*)d_in[0];
    const float* L   = (const float*)d_in[1];
    const float* Vw  = (const float*)d_in[2];
    const float* Vc  = (const float*)d_in[3];
    const int*   Cd  = (const int*)  d_in[4];
    const float* Cid = (const float*)d_in[5];
    const float* Cm  = (const float*)d_in[6];
    float* out = (float*)d_out;

    prep_kernel <<<(B * E + 255) / 256, 256>>>(Vp, L, Vw, Vc, Cd, Cid, out);
    gemm_kernel <<<N_TILES * E_SPLITS, GB_THREADS>>>(Cm);
    final_kernel<<<(B * NV + 255) / 256, 256>>>(Vp, Vw, out);
}